// round 1
// baseline (speedup 1.0000x reference)
#include <cuda_runtime.h>
#include <math.h>

#define B_    8
#define N_    1024
#define DIM_  768
#define NH_   12
#define HD_   64
#define QKVC_ 2304

// Scratch (allocation-free rule: __device__ globals)
static __device__ float g_qkv[(size_t)B_ * N_ * QKVC_];   // [B*N, 2304]
static __device__ float g_att[(size_t)B_ * N_ * DIM_];    // [B*N, 768]

// ---------------------------------------------------------------------------
// SGEMM: C[M,Nc] = A[M,K] @ W[K,Nc] (+ bias). 128x128 tile, BK=8, 256 thr,
// 8x8 per-thread microtile (split 4+4 halves for conflict-free smem access).
// Requires: M%128==0, Nc%128==0, K%8==0, all float4-aligned. True here.
// ---------------------------------------------------------------------------
__global__ void __launch_bounds__(256) sgemm_bias(
    const float* __restrict__ A, const float* __restrict__ W,
    const float* __restrict__ bias, float* __restrict__ C,
    int M, int Nc, int K)
{
    __shared__ float As[8][132];   // transposed A tile, padded: conflict-free
    __shared__ float Bs[8][128];

    const int tid  = threadIdx.x;
    const int m0   = blockIdx.y << 7;
    const int n0   = blockIdx.x << 7;
    const int arow = tid >> 1;            // 0..127
    const int acol = (tid & 1) << 2;      // 0 or 4
    const int brow = tid >> 5;            // 0..7
    const int bcol = (tid & 31) << 2;     // 0..124
    const int ty   = tid >> 4;            // 0..15
    const int tx   = tid & 15;            // 0..15

    const float* Ap = A + (size_t)(m0 + arow) * K + acol;
    const float* Wp = W + (size_t)brow * Nc + n0 + bcol;

    float acc[8][8];
#pragma unroll
    for (int i = 0; i < 8; ++i)
#pragma unroll
        for (int j = 0; j < 8; ++j) acc[i][j] = 0.f;

    for (int k0 = 0; k0 < K; k0 += 8) {
        float4 a4 = *(const float4*)(Ap + k0);
        float4 b4 = *(const float4*)(Wp + (size_t)k0 * Nc);
        As[acol + 0][arow] = a4.x;
        As[acol + 1][arow] = a4.y;
        As[acol + 2][arow] = a4.z;
        As[acol + 3][arow] = a4.w;
        *(float4*)&Bs[brow][bcol] = b4;
        __syncthreads();
#pragma unroll
        for (int kk = 0; kk < 8; ++kk) {
            float av[8], bv[8];
            *(float4*)&av[0] = *(const float4*)&As[kk][ty * 4];
            *(float4*)&av[4] = *(const float4*)&As[kk][64 + ty * 4];
            *(float4*)&bv[0] = *(const float4*)&Bs[kk][tx * 4];
            *(float4*)&bv[4] = *(const float4*)&Bs[kk][64 + tx * 4];
#pragma unroll
            for (int i = 0; i < 8; ++i)
#pragma unroll
                for (int j = 0; j < 8; ++j)
                    acc[i][j] = fmaf(av[i], bv[j], acc[i][j]);
        }
        __syncthreads();
    }

#pragma unroll
    for (int ih = 0; ih < 2; ++ih)
#pragma unroll
        for (int i = 0; i < 4; ++i) {
            int row = m0 + ih * 64 + ty * 4 + i;
#pragma unroll
            for (int jh = 0; jh < 2; ++jh) {
                int col = n0 + jh * 64 + tx * 4;
                float4 v;
                v.x = acc[ih * 4 + i][jh * 4 + 0];
                v.y = acc[ih * 4 + i][jh * 4 + 1];
                v.z = acc[ih * 4 + i][jh * 4 + 2];
                v.w = acc[ih * 4 + i][jh * 4 + 3];
                if (bias) {
                    v.x += bias[col + 0];
                    v.y += bias[col + 1];
                    v.z += bias[col + 2];
                    v.w += bias[col + 3];
                }
                *(float4*)(C + (size_t)row * Nc + col) = v;
            }
        }
}

// ---------------------------------------------------------------------------
// Flash-style attention. One block = (b, h, 64-row q-tile). Bk = 64, D = 64.
// 256 threads; thread (ty,tx) owns a 4x4 tile of S / O (rows ty*4, cols tx*4).
// Q and K stored TRANSPOSED in smem ([d][r], stride 68) so the S inner loop is
// pure conflict-free float4 LDS. P is written into the K buffer (K dead after
// S). Online softmax across 16-key-column lanes via shfl butterflies.
// out layout: [B, N, H*D] so the projection GEMM can consume it directly.
// ---------------------------------------------------------------------------
#define LDS_ (68)
__global__ void __launch_bounds__(256) attn_fwd(
    const float* __restrict__ qkv, float* __restrict__ out)
{
    extern __shared__ float sm[];
    float* Qt   = sm;                 // Qt[d*68 + r], scaled
    float* KtPs = sm + 64 * LDS_;     // Kt[d*68 + r]  then  Ps[r*68 + j]
    float* Vs   = sm + 2 * 64 * LDS_; // Vs[r*68 + d]

    const int bh  = blockIdx.y;
    const int b   = bh / NH_;
    const int h   = bh - b * NH_;
    const int qt  = blockIdx.x;
    const int tid = threadIdx.x;
    const int ty  = tid >> 4;
    const int tx  = tid & 15;
    const int r0  = ty * 4;
    const int c0  = tx * 4;

    const size_t rowbase = (size_t)b * N_;
    const float* qb = qkv + (rowbase + (size_t)qt * 64) * QKVC_ + h * HD_;
    const float* kb = qkv + rowbase * QKVC_ + DIM_ + h * HD_;
    const float* vb = qkv + rowbase * QKVC_ + 2 * DIM_ + h * HD_;

    const float scale = 0.125f;  // 1/sqrt(64)

    // Load Q tile, transposed & pre-scaled (gmem coalesced on d)
    {
        const int r = tid >> 6;    // 0..3
        const int d = tid & 63;
#pragma unroll
        for (int p = 0; p < 16; ++p) {
            int rr = p * 4 + r;
            Qt[d * LDS_ + rr] = qb[(size_t)rr * QKVC_ + d] * scale;
        }
    }

    float m[4], l[4], o[4][4];
#pragma unroll
    for (int i = 0; i < 4; ++i) {
        m[i] = -1e30f; l[i] = 0.f;
#pragma unroll
        for (int j = 0; j < 4; ++j) o[i][j] = 0.f;
    }

    for (int j0 = 0; j0 < N_; j0 += 64) {
        __syncthreads();   // previous P@V done (and Qt ready on iter 0)
        {
            const int r = tid >> 6;
            const int d = tid & 63;
#pragma unroll
            for (int p = 0; p < 16; ++p) {
                int rr = p * 4 + r;
                float kvl = kb[(size_t)(j0 + rr) * QKVC_ + d];
                float vvl = vb[(size_t)(j0 + rr) * QKVC_ + d];
                KtPs[d * LDS_ + rr] = kvl;   // K transposed
                Vs[rr * LDS_ + d]   = vvl;   // V natural
            }
        }
        __syncthreads();

        // S = (Q*scale) @ K^T  — 4x4 per thread
        float s[4][4];
#pragma unroll
        for (int i = 0; i < 4; ++i)
#pragma unroll
            for (int j = 0; j < 4; ++j) s[i][j] = 0.f;

#pragma unroll 8
        for (int d = 0; d < 64; ++d) {
            float4 qa = *(const float4*)(Qt + d * LDS_ + r0);
            float4 kk = *(const float4*)(KtPs + d * LDS_ + c0);
            float qv[4] = {qa.x, qa.y, qa.z, qa.w};
            float kv[4] = {kk.x, kk.y, kk.z, kk.w};
#pragma unroll
            for (int i = 0; i < 4; ++i)
#pragma unroll
                for (int j = 0; j < 4; ++j)
                    s[i][j] = fmaf(qv[i], kv[j], s[i][j]);
        }
        __syncthreads();   // everyone done reading Kt before we alias it as Ps

        // Online softmax update (row reductions across tx within 16-lane group)
#pragma unroll
        for (int i = 0; i < 4; ++i) {
            float rm = fmaxf(fmaxf(s[i][0], s[i][1]), fmaxf(s[i][2], s[i][3]));
#pragma unroll
            for (int k = 8; k >= 1; k >>= 1)
                rm = fmaxf(rm, __shfl_xor_sync(0xffffffffu, rm, k));
            float mn    = fmaxf(m[i], rm);
            float alpha = __expf(m[i] - mn);
            m[i] = mn;
            float rs = 0.f;
#pragma unroll
            for (int j = 0; j < 4; ++j) {
                float p = __expf(s[i][j] - mn);
                s[i][j] = p;
                rs += p;
            }
#pragma unroll
            for (int k = 8; k >= 1; k >>= 1)
                rs += __shfl_xor_sync(0xffffffffu, rs, k);
            l[i] = l[i] * alpha + rs;
#pragma unroll
            for (int j = 0; j < 4; ++j) o[i][j] *= alpha;
        }

        // Stash P into the dead K buffer
#pragma unroll
        for (int i = 0; i < 4; ++i)
            *(float4*)(KtPs + (r0 + i) * LDS_ + c0) =
                make_float4(s[i][0], s[i][1], s[i][2], s[i][3]);
        __syncthreads();

        // O += P @ V
#pragma unroll 4
        for (int j = 0; j < 64; ++j) {
            float4 v4 = *(const float4*)(Vs + j * LDS_ + c0);
            float p0 = KtPs[(r0 + 0) * LDS_ + j];
            float p1 = KtPs[(r0 + 1) * LDS_ + j];
            float p2 = KtPs[(r0 + 2) * LDS_ + j];
            float p3 = KtPs[(r0 + 3) * LDS_ + j];
            o[0][0] = fmaf(p0, v4.x, o[0][0]); o[0][1] = fmaf(p0, v4.y, o[0][1]);
            o[0][2] = fmaf(p0, v4.z, o[0][2]); o[0][3] = fmaf(p0, v4.w, o[0][3]);
            o[1][0] = fmaf(p1, v4.x, o[1][0]); o[1][1] = fmaf(p1, v4.y, o[1][1]);
            o[1][2] = fmaf(p1, v4.z, o[1][2]); o[1][3] = fmaf(p1, v4.w, o[1][3]);
            o[2][0] = fmaf(p2, v4.x, o[2][0]); o[2][1] = fmaf(p2, v4.y, o[2][1]);
            o[2][2] = fmaf(p2, v4.z, o[2][2]); o[2][3] = fmaf(p2, v4.w, o[2][3]);
            o[3][0] = fmaf(p3, v4.x, o[3][0]); o[3][1] = fmaf(p3, v4.y, o[3][1]);
            o[3][2] = fmaf(p3, v4.z, o[3][2]); o[3][3] = fmaf(p3, v4.w, o[3][3]);
        }
    }

    // Normalize and write out: out[b, n, h*64 + c]
    float* ob = out + (rowbase + (size_t)qt * 64) * DIM_ + h * HD_;
#pragma unroll
    for (int i = 0; i < 4; ++i) {
        float inv = 1.0f / l[i];
        float4 v = make_float4(o[i][0] * inv, o[i][1] * inv,
                               o[i][2] * inv, o[i][3] * inv);
        *(float4*)(ob + (size_t)(r0 + i) * DIM_ + c0) = v;
    }
}

// ---------------------------------------------------------------------------
extern "C" void kernel_launch(void* const* d_in, const int* in_sizes, int n_in,
                              void* d_out, int out_size)
{
    const float* x      = (const float*)d_in[0];   // [8,1024,768]
    const float* w_qkv  = (const float*)d_in[1];   // [768, 2304]
    const float* w_proj = (const float*)d_in[2];   // [768, 768]
    const float* b_proj = (const float*)d_in[3];   // [768]
    float* out = (float*)d_out;                    // [8,1024,768]

    float* qkv_ptr = nullptr;
    float* att_ptr = nullptr;
    cudaGetSymbolAddress((void**)&qkv_ptr, g_qkv);
    cudaGetSymbolAddress((void**)&att_ptr, g_att);

    const int M = B_ * N_;   // 8192

    // 1) QKV projection: [8192,768] @ [768,2304] -> g_qkv
    sgemm_bias<<<dim3(QKVC_ / 128, M / 128), 256>>>(
        x, w_qkv, nullptr, qkv_ptr, M, QKVC_, DIM_);

    // 2) Attention -> g_att [B, N, 768]
    const int smem = 3 * 64 * LDS_ * (int)sizeof(float);  // 52224 B
    cudaFuncSetAttribute(attn_fwd, cudaFuncAttributeMaxDynamicSharedMemorySize, smem);
    attn_fwd<<<dim3(N_ / 64, B_ * NH_), 256, smem>>>(qkv_ptr, att_ptr);

    // 3) Output projection + bias: [8192,768] @ [768,768] + b -> out
    sgemm_bias<<<dim3(DIM_ / 128, M / 128), 256>>>(
        att_ptr, w_proj, b_proj, out, M, DIM_, DIM_);
}

// round 3
// speedup vs baseline: 1.4477x; 1.4477x over previous
#include <cuda_runtime.h>
#include <cuda_bf16.h>
#include <cstdint>
#include <math.h>

#define B_    8
#define N_    1024
#define DIM_  768
#define NH_   12
#define HD_   64
#define QKVC_ 2304
#define MROWS (B_*N_)   // 8192

// ---------------- scratch (__device__ globals; allocation-free rule) -------
static __device__ float g_qkv[(size_t)MROWS * QKVC_];
static __device__ float g_att[(size_t)MROWS * DIM_];
static __device__ __nv_bfloat16 g_x_hi[(size_t)MROWS * DIM_];
static __device__ __nv_bfloat16 g_x_lo[(size_t)MROWS * DIM_];
static __device__ __nv_bfloat16 g_a_hi[(size_t)MROWS * DIM_];
static __device__ __nv_bfloat16 g_a_lo[(size_t)MROWS * DIM_];
static __device__ __nv_bfloat16 g_wqT_hi[(size_t)QKVC_ * DIM_];
static __device__ __nv_bfloat16 g_wqT_lo[(size_t)QKVC_ * DIM_];
static __device__ __nv_bfloat16 g_wpT_hi[(size_t)DIM_ * DIM_];
static __device__ __nv_bfloat16 g_wpT_lo[(size_t)DIM_ * DIM_];

// ---------------- warp-MMA helpers (base ISA, sm_80+) ----------------------
__device__ __forceinline__ uint32_t smem_u32(const void* p) {
    uint32_t a;
    asm("{ .reg .u64 t; cvta.to.shared.u64 t, %1; cvt.u32.u64 %0, t; }" : "=r"(a) : "l"(p));
    return a;
}
__device__ __forceinline__ void ldsm_x4(uint32_t* r, uint32_t addr) {
    asm volatile("ldmatrix.sync.aligned.m8n8.x4.shared.b16 {%0,%1,%2,%3}, [%4];"
                 : "=r"(r[0]), "=r"(r[1]), "=r"(r[2]), "=r"(r[3]) : "r"(addr));
}
__device__ __forceinline__ void mma_bf16(float* c, const uint32_t* a,
                                         uint32_t b0, uint32_t b1) {
    asm volatile("mma.sync.aligned.m16n8k16.row.col.f32.bf16.bf16.f32 "
        "{%0,%1,%2,%3}, {%4,%5,%6,%7}, {%8,%9}, {%0,%1,%2,%3};"
        : "+f"(c[0]), "+f"(c[1]), "+f"(c[2]), "+f"(c[3])
        : "r"(a[0]), "r"(a[1]), "r"(a[2]), "r"(a[3]), "r"(b0), "r"(b1));
}

// ---------------- conversion kernels ---------------------------------------
__global__ void __launch_bounds__(256) split_f32(
    const float* __restrict__ in, __nv_bfloat16* __restrict__ hi,
    __nv_bfloat16* __restrict__ lo, int n4)
{
    int i = blockIdx.x * blockDim.x + threadIdx.x;
    if (i >= n4) return;
    float4 v = ((const float4*)in)[i];
    float a[4] = {v.x, v.y, v.z, v.w};
    __nv_bfloat16 h[4], l[4];
#pragma unroll
    for (int j = 0; j < 4; ++j) {
        h[j] = __float2bfloat16(a[j]);
        l[j] = __float2bfloat16(a[j] - __bfloat162float(h[j]));
    }
    __nv_bfloat162 h0, h1, l0, l1;
    h0.x = h[0]; h0.y = h[1]; h1.x = h[2]; h1.y = h[3];
    l0.x = l[0]; l0.y = l[1]; l1.x = l[2]; l1.y = l[3];
    ((__nv_bfloat162*)hi)[2 * i]     = h0;
    ((__nv_bfloat162*)hi)[2 * i + 1] = h1;
    ((__nv_bfloat162*)lo)[2 * i]     = l0;
    ((__nv_bfloat162*)lo)[2 * i + 1] = l1;
}

// W[K,Nc] fp32 -> WT_hi/lo[Nc,K] bf16
__global__ void __launch_bounds__(256) transpose_split(
    const float* __restrict__ W, __nv_bfloat16* __restrict__ hiT,
    __nv_bfloat16* __restrict__ loT, int K, int Nc)
{
    __shared__ float t[32][33];
    const int n0 = blockIdx.x * 32, k0 = blockIdx.y * 32;
    const int tx = threadIdx.x & 31, ty = threadIdx.x >> 5;
#pragma unroll
    for (int i = 0; i < 32; i += 8)
        t[ty + i][tx] = W[(size_t)(k0 + ty + i) * Nc + n0 + tx];
    __syncthreads();
#pragma unroll
    for (int i = 0; i < 32; i += 8) {
        float v = t[tx][ty + i];
        __nv_bfloat16 h = __float2bfloat16(v);
        __nv_bfloat16 l = __float2bfloat16(v - __bfloat162float(h));
        size_t o = (size_t)(n0 + ty + i) * K + k0 + tx;
        hiT[o] = h;
        loT[o] = l;
    }
}

// ---------------- HMMA bf16x3 GEMM ------------------------------------------
// C[M,Nc] = Ahi@B^T + Ahi@Blo^T + Alo@Bhi^T (+bias), fp32 accum.
// A: [M,K] bf16 row-major. BT: [Nc,K] bf16 (K contiguous -> mma .col operand).
// CTA tile 128x128, BK=32, 8 warps (4m x 2n), warp tile 32x64.
#define GBK      32
#define TSTRIDE  80                 // 32 bf16 = 64B data + 16B pad (5 mod 8 swizzle)
#define TILE_B   (128 * TSTRIDE)    // 10240

__device__ __forceinline__ void load_tile(
    char* __restrict__ dst, const __nv_bfloat16* __restrict__ g, int ldK, int tid)
{
#pragma unroll
    for (int it = 0; it < 2; ++it) {
        int c   = tid + it * 256;      // 0..511
        int row = c >> 2, c4 = c & 3;
        uint4 v = *(const uint4*)(g + (size_t)row * ldK + c4 * 8);
        *(uint4*)(dst + row * TSTRIDE + c4 * 16) = v;
    }
}

__global__ void __launch_bounds__(256, 2) gemm_bf16x3(
    const __nv_bfloat16* __restrict__ Ahi, const __nv_bfloat16* __restrict__ Alo,
    const __nv_bfloat16* __restrict__ BhiT, const __nv_bfloat16* __restrict__ BloT,
    const float* __restrict__ bias, float* __restrict__ C, int Nc, int K)
{
    __shared__ __align__(128) char smem[4 * TILE_B];   // Ahi, Alo, Bhi, Blo
    char* sAh = smem;
    char* sAl = smem + TILE_B;
    char* sBh = smem + 2 * TILE_B;
    char* sBl = smem + 3 * TILE_B;

    const int tid = threadIdx.x, wid = tid >> 5, lid = tid & 31;
    const int wm = wid >> 1, wn = wid & 1;
    const int m0 = blockIdx.y << 7, n0 = blockIdx.x << 7;

    const __nv_bfloat16* pAh = Ahi  + (size_t)m0 * K;
    const __nv_bfloat16* pAl = Alo  + (size_t)m0 * K;
    const __nv_bfloat16* pBh = BhiT + (size_t)n0 * K;
    const __nv_bfloat16* pBl = BloT + (size_t)n0 * K;

    float acc[2][8][4];
#pragma unroll
    for (int i = 0; i < 2; ++i)
#pragma unroll
        for (int j = 0; j < 8; ++j)
#pragma unroll
            for (int k = 0; k < 4; ++k) acc[i][j][k] = 0.f;

    // ldmatrix base addresses (per-lane)
    const uint32_t sb = smem_u32(smem);
    const int arow = wm * 32 + (lid & 15);
    const uint32_t aoff = arow * TSTRIDE + ((lid >> 4) << 4);
    const int brow = wn * 64 + (lid & 7) + ((lid >> 4) << 3);
    const uint32_t boff = brow * TSTRIDE + (((lid >> 3) & 1) << 4);

    for (int k0 = 0; k0 < K; k0 += GBK) {
        __syncthreads();
        load_tile(sAh, pAh + k0, K, tid);
        load_tile(sAl, pAl + k0, K, tid);
        load_tile(sBh, pBh + k0, K, tid);
        load_tile(sBl, pBl + k0, K, tid);
        __syncthreads();

#pragma unroll
        for (int kc = 0; kc < 2; ++kc) {
            const uint32_t kb = kc * 32;  // 16 bf16 = 32B per k-chunk
            uint32_t ah[2][4], al[2][4];
#pragma unroll
            for (int im = 0; im < 2; ++im) {
                ldsm_x4(ah[im], sb + 0 * TILE_B + aoff + im * 16 * TSTRIDE + kb);
                ldsm_x4(al[im], sb + 1 * TILE_B + aoff + im * 16 * TSTRIDE + kb);
            }
#pragma unroll
            for (int p = 0; p < 4; ++p) {
                uint32_t bh[4], bl[4];
                ldsm_x4(bh, sb + 2 * TILE_B + boff + p * 16 * TSTRIDE + kb);
                ldsm_x4(bl, sb + 3 * TILE_B + boff + p * 16 * TSTRIDE + kb);
                const int nt0 = p * 2, nt1 = p * 2 + 1;
#pragma unroll
                for (int im = 0; im < 2; ++im) {
                    mma_bf16(acc[im][nt0], ah[im], bh[0], bh[1]);
                    mma_bf16(acc[im][nt0], ah[im], bl[0], bl[1]);
                    mma_bf16(acc[im][nt0], al[im], bh[0], bh[1]);
                    mma_bf16(acc[im][nt1], ah[im], bh[2], bh[3]);
                    mma_bf16(acc[im][nt1], ah[im], bl[2], bl[3]);
                    mma_bf16(acc[im][nt1], al[im], bh[2], bh[3]);
                }
            }
        }
    }

    // epilogue: c frag -> gmem (+bias)
    const int g = lid >> 2, q = lid & 3;
#pragma unroll
    for (int im = 0; im < 2; ++im) {
        const int row0 = m0 + wm * 32 + im * 16 + g;
#pragma unroll
        for (int nt = 0; nt < 8; ++nt) {
            const int col = n0 + wn * 64 + nt * 8 + q * 2;
            float b0 = 0.f, b1 = 0.f;
            if (bias) { b0 = bias[col]; b1 = bias[col + 1]; }
            float2 v0 = make_float2(acc[im][nt][0] + b0, acc[im][nt][1] + b1);
            float2 v1 = make_float2(acc[im][nt][2] + b0, acc[im][nt][3] + b1);
            *(float2*)(C + (size_t)row0 * Nc + col)       = v0;
            *(float2*)(C + (size_t)(row0 + 8) * Nc + col) = v1;
        }
    }
}

// ---------------------------------------------------------------------------
// Flash-style fp32 attention (unchanged).
// ---------------------------------------------------------------------------
#define LDS_ (68)
__global__ void __launch_bounds__(256) attn_fwd(
    const float* __restrict__ qkv, float* __restrict__ out)
{
    extern __shared__ float sm[];
    float* Qt   = sm;
    float* KtPs = sm + 64 * LDS_;
    float* Vs   = sm + 2 * 64 * LDS_;

    const int bh  = blockIdx.y;
    const int b   = bh / NH_;
    const int h   = bh - b * NH_;
    const int qt  = blockIdx.x;
    const int tid = threadIdx.x;
    const int ty  = tid >> 4;
    const int tx  = tid & 15;
    const int r0  = ty * 4;
    const int c0  = tx * 4;

    const size_t rowbase = (size_t)b * N_;
    const float* qb = qkv + (rowbase + (size_t)qt * 64) * QKVC_ + h * HD_;
    const float* kb = qkv + rowbase * QKVC_ + DIM_ + h * HD_;
    const float* vb = qkv + rowbase * QKVC_ + 2 * DIM_ + h * HD_;

    const float scale = 0.125f;

    {
        const int r = tid >> 6;
        const int d = tid & 63;
#pragma unroll
        for (int p = 0; p < 16; ++p) {
            int rr = p * 4 + r;
            Qt[d * LDS_ + rr] = qb[(size_t)rr * QKVC_ + d] * scale;
        }
    }

    float m[4], l[4], o[4][4];
#pragma unroll
    for (int i = 0; i < 4; ++i) {
        m[i] = -1e30f; l[i] = 0.f;
#pragma unroll
        for (int j = 0; j < 4; ++j) o[i][j] = 0.f;
    }

    for (int j0 = 0; j0 < N_; j0 += 64) {
        __syncthreads();
        {
            const int r = tid >> 6;
            const int d = tid & 63;
#pragma unroll
            for (int p = 0; p < 16; ++p) {
                int rr = p * 4 + r;
                float kvl = kb[(size_t)(j0 + rr) * QKVC_ + d];
                float vvl = vb[(size_t)(j0 + rr) * QKVC_ + d];
                KtPs[d * LDS_ + rr] = kvl;
                Vs[rr * LDS_ + d]   = vvl;
            }
        }
        __syncthreads();

        float s[4][4];
#pragma unroll
        for (int i = 0; i < 4; ++i)
#pragma unroll
            for (int j = 0; j < 4; ++j) s[i][j] = 0.f;

#pragma unroll 8
        for (int d = 0; d < 64; ++d) {
            float4 qa = *(const float4*)(Qt + d * LDS_ + r0);
            float4 kk = *(const float4*)(KtPs + d * LDS_ + c0);
            float qv[4] = {qa.x, qa.y, qa.z, qa.w};
            float kv[4] = {kk.x, kk.y, kk.z, kk.w};
#pragma unroll
            for (int i = 0; i < 4; ++i)
#pragma unroll
                for (int j = 0; j < 4; ++j)
                    s[i][j] = fmaf(qv[i], kv[j], s[i][j]);
        }
        __syncthreads();

#pragma unroll
        for (int i = 0; i < 4; ++i) {
            float rm = fmaxf(fmaxf(s[i][0], s[i][1]), fmaxf(s[i][2], s[i][3]));
#pragma unroll
            for (int k = 8; k >= 1; k >>= 1)
                rm = fmaxf(rm, __shfl_xor_sync(0xffffffffu, rm, k));
            float mn    = fmaxf(m[i], rm);
            float alpha = __expf(m[i] - mn);
            m[i] = mn;
            float rs = 0.f;
#pragma unroll
            for (int j = 0; j < 4; ++j) {
                float p = __expf(s[i][j] - mn);
                s[i][j] = p;
                rs += p;
            }
#pragma unroll
            for (int k = 8; k >= 1; k >>= 1)
                rs += __shfl_xor_sync(0xffffffffu, rs, k);
            l[i] = l[i] * alpha + rs;
#pragma unroll
            for (int j = 0; j < 4; ++j) o[i][j] *= alpha;
        }

#pragma unroll
        for (int i = 0; i < 4; ++i)
            *(float4*)(KtPs + (r0 + i) * LDS_ + c0) =
                make_float4(s[i][0], s[i][1], s[i][2], s[i][3]);
        __syncthreads();

#pragma unroll 4
        for (int j = 0; j < 64; ++j) {
            float4 v4 = *(const float4*)(Vs + j * LDS_ + c0);
            float p0 = KtPs[(r0 + 0) * LDS_ + j];
            float p1 = KtPs[(r0 + 1) * LDS_ + j];
            float p2 = KtPs[(r0 + 2) * LDS_ + j];
            float p3 = KtPs[(r0 + 3) * LDS_ + j];
            o[0][0] = fmaf(p0, v4.x, o[0][0]); o[0][1] = fmaf(p0, v4.y, o[0][1]);
            o[0][2] = fmaf(p0, v4.z, o[0][2]); o[0][3] = fmaf(p0, v4.w, o[0][3]);
            o[1][0] = fmaf(p1, v4.x, o[1][0]); o[1][1] = fmaf(p1, v4.y, o[1][1]);
            o[1][2] = fmaf(p1, v4.z, o[1][2]); o[1][3] = fmaf(p1, v4.w, o[1][3]);
            o[2][0] = fmaf(p2, v4.x, o[2][0]); o[2][1] = fmaf(p2, v4.y, o[2][1]);
            o[2][2] = fmaf(p2, v4.z, o[2][2]); o[2][3] = fmaf(p2, v4.w, o[2][3]);
            o[3][0] = fmaf(p3, v4.x, o[3][0]); o[3][1] = fmaf(p3, v4.y, o[3][1]);
            o[3][2] = fmaf(p3, v4.z, o[3][2]); o[3][3] = fmaf(p3, v4.w, o[3][3]);
        }
    }

    float* ob = out + (rowbase + (size_t)qt * 64) * DIM_ + h * HD_;
#pragma unroll
    for (int i = 0; i < 4; ++i) {
        float inv = 1.0f / l[i];
        float4 v = make_float4(o[i][0] * inv, o[i][1] * inv,
                               o[i][2] * inv, o[i][3] * inv);
        *(float4*)(ob + (size_t)(r0 + i) * DIM_ + c0) = v;
    }
}

// ---------------------------------------------------------------------------
extern "C" void kernel_launch(void* const* d_in, const int* in_sizes, int n_in,
                              void* d_out, int out_size)
{
    const float* x      = (const float*)d_in[0];
    const float* w_qkv  = (const float*)d_in[1];
    const float* w_proj = (const float*)d_in[2];
    const float* b_proj = (const float*)d_in[3];
    float* out = (float*)d_out;

    float *qkv_ptr, *att_ptr;
    __nv_bfloat16 *xh, *xl, *ah, *al, *wqh, *wql, *wph, *wpl;
    cudaGetSymbolAddress((void**)&qkv_ptr, g_qkv);
    cudaGetSymbolAddress((void**)&att_ptr, g_att);
    cudaGetSymbolAddress((void**)&xh, g_x_hi);
    cudaGetSymbolAddress((void**)&xl, g_x_lo);
    cudaGetSymbolAddress((void**)&ah, g_a_hi);
    cudaGetSymbolAddress((void**)&al, g_a_lo);
    cudaGetSymbolAddress((void**)&wqh, g_wqT_hi);
    cudaGetSymbolAddress((void**)&wql, g_wqT_lo);
    cudaGetSymbolAddress((void**)&wph, g_wpT_hi);
    cudaGetSymbolAddress((void**)&wpl, g_wpT_lo);

    const int M = MROWS;  // 8192

    // 0) splits / transposed splits
    {
        int n4 = M * DIM_ / 4;
        split_f32<<<(n4 + 255) / 256, 256>>>(x, xh, xl, n4);
        transpose_split<<<dim3(QKVC_ / 32, DIM_ / 32), 256>>>(w_qkv, wqh, wql, DIM_, QKVC_);
        transpose_split<<<dim3(DIM_ / 32, DIM_ / 32), 256>>>(w_proj, wph, wpl, DIM_, DIM_);
    }

    // 1) QKV projection (HMMA bf16x3): [8192,768]@[768,2304] -> g_qkv
    gemm_bf16x3<<<dim3(QKVC_ / 128, M / 128), 256>>>(
        xh, xl, wqh, wql, nullptr, qkv_ptr, QKVC_, DIM_);

    // 2) attention (fp32) -> g_att
    const int smem = 3 * 64 * LDS_ * (int)sizeof(float);
    cudaFuncSetAttribute(attn_fwd, cudaFuncAttributeMaxDynamicSharedMemorySize, smem);
    attn_fwd<<<dim3(N_ / 64, B_ * NH_), 256, smem>>>(qkv_ptr, att_ptr);

    // 3) split attention output, then proj (HMMA bf16x3) + bias -> out
    {
        int n4 = M * DIM_ / 4;
        split_f32<<<(n4 + 255) / 256, 256>>>(att_ptr, ah, al, n4);
    }
    gemm_bf16x3<<<dim3(DIM_ / 128, M / 128), 256>>>(
        ah, al, wph, wpl, b_proj, out, DIM_, DIM_);
}

// round 4
// speedup vs baseline: 2.6258x; 1.8137x over previous
#include <cuda_runtime.h>
#include <cuda_bf16.h>
#include <cstdint>
#include <math.h>

#define B_    8
#define N_    1024
#define DIM_  768
#define NH_   12
#define HD_   64
#define QKVC_ 2304
#define MROWS (B_*N_)   // 8192

// ---------------- scratch (__device__ globals) ------------------------------
static __device__ __nv_bfloat16 g_x_hi[(size_t)MROWS * DIM_];
static __device__ __nv_bfloat16 g_x_lo[(size_t)MROWS * DIM_];
static __device__ __nv_bfloat16 g_a_hi[(size_t)MROWS * DIM_];
static __device__ __nv_bfloat16 g_a_lo[(size_t)MROWS * DIM_];
static __device__ __nv_bfloat16 g_wqT_hi[(size_t)QKVC_ * DIM_];
static __device__ __nv_bfloat16 g_wqT_lo[(size_t)QKVC_ * DIM_];
static __device__ __nv_bfloat16 g_wpT_hi[(size_t)DIM_ * DIM_];
static __device__ __nv_bfloat16 g_wpT_lo[(size_t)DIM_ * DIM_];
// per-head split qkv: [bh][n][d], bh = b*12+h
static __device__ __nv_bfloat16 g_q_hi[(size_t)MROWS * DIM_];
static __device__ __nv_bfloat16 g_q_lo[(size_t)MROWS * DIM_];
static __device__ __nv_bfloat16 g_k_hi[(size_t)MROWS * DIM_];
static __device__ __nv_bfloat16 g_k_lo[(size_t)MROWS * DIM_];
static __device__ __nv_bfloat16 g_v_hi[(size_t)MROWS * DIM_];
static __device__ __nv_bfloat16 g_v_lo[(size_t)MROWS * DIM_];

// ---------------- helpers ----------------------------------------------------
__device__ __forceinline__ uint32_t smem_u32(const void* p) {
    uint32_t a;
    asm("{ .reg .u64 t; cvta.to.shared.u64 t, %1; cvt.u32.u64 %0, t; }" : "=r"(a) : "l"(p));
    return a;
}
__device__ __forceinline__ void ldsm_x4(uint32_t* r, uint32_t addr) {
    asm volatile("ldmatrix.sync.aligned.m8n8.x4.shared.b16 {%0,%1,%2,%3}, [%4];"
                 : "=r"(r[0]), "=r"(r[1]), "=r"(r[2]), "=r"(r[3]) : "r"(addr));
}
__device__ __forceinline__ void ldsm_x4_t(uint32_t* r, uint32_t addr) {
    asm volatile("ldmatrix.sync.aligned.m8n8.x4.trans.shared.b16 {%0,%1,%2,%3}, [%4];"
                 : "=r"(r[0]), "=r"(r[1]), "=r"(r[2]), "=r"(r[3]) : "r"(addr));
}
__device__ __forceinline__ void mma_bf16(float* c, const uint32_t* a,
                                         uint32_t b0, uint32_t b1) {
    asm volatile("mma.sync.aligned.m16n8k16.row.col.f32.bf16.bf16.f32 "
        "{%0,%1,%2,%3}, {%4,%5,%6,%7}, {%8,%9}, {%0,%1,%2,%3};"
        : "+f"(c[0]), "+f"(c[1]), "+f"(c[2]), "+f"(c[3])
        : "r"(a[0]), "r"(a[1]), "r"(a[2]), "r"(a[3]), "r"(b0), "r"(b1));
}
__device__ __forceinline__ uint32_t pack_bf16x2(float lo, float hi) {
    uint32_t d;
    asm("cvt.rn.bf16x2.f32 %0, %1, %2;" : "=r"(d) : "f"(hi), "f"(lo));
    return d;
}
// split two fp32 into packed bf16x2 hi + bf16x2 residual
__device__ __forceinline__ void split_pack(float v0, float v1,
                                           uint32_t& h, uint32_t& l) {
    h = pack_bf16x2(v0, v1);
    float f0 = __uint_as_float(h << 16);
    float f1 = __uint_as_float(h & 0xffff0000u);
    l = pack_bf16x2(v0 - f0, v1 - f1);
}
#define CP_ASYNC16(dst, src) \
    asm volatile("cp.async.cg.shared.global [%0], [%1], 16;" :: "r"(dst), "l"(src) : "memory")
#define CP_COMMIT() asm volatile("cp.async.commit_group;" ::: "memory")
#define CP_WAIT(n)  asm volatile("cp.async.wait_group %0;" :: "n"(n) : "memory")

// ---------------- conversion kernels ----------------------------------------
__global__ void __launch_bounds__(256) split_f32(
    const float* __restrict__ in, __nv_bfloat16* __restrict__ hi,
    __nv_bfloat16* __restrict__ lo, int n4)
{
    int i = blockIdx.x * blockDim.x + threadIdx.x;
    if (i >= n4) return;
    float4 v = ((const float4*)in)[i];
    uint32_t h0, l0, h1, l1;
    split_pack(v.x, v.y, h0, l0);
    split_pack(v.z, v.w, h1, l1);
    ((uint32_t*)hi)[2 * i]     = h0;
    ((uint32_t*)hi)[2 * i + 1] = h1;
    ((uint32_t*)lo)[2 * i]     = l0;
    ((uint32_t*)lo)[2 * i + 1] = l1;
}

__global__ void __launch_bounds__(256) transpose_split(
    const float* __restrict__ W, __nv_bfloat16* __restrict__ hiT,
    __nv_bfloat16* __restrict__ loT, int K, int Nc)
{
    __shared__ float t[32][33];
    const int n0 = blockIdx.x * 32, k0 = blockIdx.y * 32;
    const int tx = threadIdx.x & 31, ty = threadIdx.x >> 5;
#pragma unroll
    for (int i = 0; i < 32; i += 8)
        t[ty + i][tx] = W[(size_t)(k0 + ty + i) * Nc + n0 + tx];
    __syncthreads();
#pragma unroll
    for (int i = 0; i < 32; i += 8) {
        float v = t[tx][ty + i];
        __nv_bfloat16 h = __float2bfloat16(v);
        __nv_bfloat16 l = __float2bfloat16(v - __bfloat162float(h));
        size_t o = (size_t)(n0 + ty + i) * K + k0 + tx;
        hiT[o] = h;
        loT[o] = l;
    }
}

// ---------------- HMMA bf16x3 GEMM (cp.async 2-stage) -----------------------
// MODE 0: fp32 C + bias. MODE 1: split-qkv epilogue into per-head buffers.
#define TSTRIDE  80
#define GT_B     10240               // 128 rows * 80
#define GSTAGE   (4 * GT_B)          // 40960
#define GEMM_SMEM (2 * GSTAGE)       // 81920

template<int MODE>
__global__ void __launch_bounds__(256, 2) gemm_bf16x3(
    const __nv_bfloat16* __restrict__ Ahi, const __nv_bfloat16* __restrict__ Alo,
    const __nv_bfloat16* __restrict__ BhiT, const __nv_bfloat16* __restrict__ BloT,
    const float* __restrict__ bias, float* __restrict__ C, int Nc, int K,
    __nv_bfloat16* qh_, __nv_bfloat16* ql_, __nv_bfloat16* kh_,
    __nv_bfloat16* kl_, __nv_bfloat16* vh_, __nv_bfloat16* vl_)
{
    extern __shared__ char gsm[];
    const uint32_t sb = smem_u32(gsm);
    const int tid = threadIdx.x, wid = tid >> 5, lid = tid & 31;
    const int wm = wid >> 1, wn = wid & 1;
    const int m0 = blockIdx.y << 7, n0 = blockIdx.x << 7;

    const __nv_bfloat16* pAh = Ahi  + (size_t)m0 * K;
    const __nv_bfloat16* pAl = Alo  + (size_t)m0 * K;
    const __nv_bfloat16* pBh = BhiT + (size_t)n0 * K;
    const __nv_bfloat16* pBl = BloT + (size_t)n0 * K;

    float acc[2][8][4];
#pragma unroll
    for (int i = 0; i < 2; ++i)
#pragma unroll
        for (int j = 0; j < 8; ++j)
#pragma unroll
            for (int k = 0; k < 4; ++k) acc[i][j][k] = 0.f;

    const int nkt = K >> 5;   // K/32

    // prefetch helper (8 cp.async per thread per tile)
    const int prow = tid >> 2, pc4 = tid & 3;
#define GPF(kt, stage) do {                                                      \
    uint32_t s0 = sb + (stage) * GSTAGE;                                         \
    _Pragma("unroll")                                                            \
    for (int half = 0; half < 2; ++half) {                                       \
        int row = prow + half * 64;                                              \
        uint32_t d = s0 + row * TSTRIDE + pc4 * 16;                              \
        size_t go = (size_t)row * K + (kt) * 32 + pc4 * 8;                       \
        CP_ASYNC16(d + 0 * GT_B, pAh + go);                                      \
        CP_ASYNC16(d + 1 * GT_B, pAl + go);                                      \
        CP_ASYNC16(d + 2 * GT_B, pBh + go);                                      \
        CP_ASYNC16(d + 3 * GT_B, pBl + go);                                      \
    }                                                                            \
    CP_COMMIT();                                                                 \
} while (0)

    GPF(0, 0);
    GPF(1, 1);

    const uint32_t aoff = (wm * 32 + (lid & 15)) * TSTRIDE + ((lid >> 4) << 4);
    const uint32_t boff = (wn * 64 + (lid & 7) + ((lid >> 4) << 3)) * TSTRIDE
                        + (((lid >> 3) & 1) << 4);

    for (int kt = 0; kt < nkt; ++kt) {
        if (kt == nkt - 1) { CP_WAIT(0); } else { CP_WAIT(1); }
        __syncthreads();
        const uint32_t st = sb + (kt & 1) * GSTAGE;

#pragma unroll
        for (int kc = 0; kc < 2; ++kc) {
            const uint32_t kb = kc * 32;
            uint32_t ah[2][4], al[2][4];
#pragma unroll
            for (int im = 0; im < 2; ++im) {
                ldsm_x4(ah[im], st + 0 * GT_B + aoff + im * 16 * TSTRIDE + kb);
                ldsm_x4(al[im], st + 1 * GT_B + aoff + im * 16 * TSTRIDE + kb);
            }
#pragma unroll
            for (int p = 0; p < 4; ++p) {
                uint32_t bh4[4], bl4[4];
                ldsm_x4(bh4, st + 2 * GT_B + boff + p * 16 * TSTRIDE + kb);
                ldsm_x4(bl4, st + 3 * GT_B + boff + p * 16 * TSTRIDE + kb);
                const int nt0 = p * 2, nt1 = p * 2 + 1;
#pragma unroll
                for (int im = 0; im < 2; ++im) {
                    mma_bf16(acc[im][nt0], ah[im], bh4[0], bh4[1]);
                    mma_bf16(acc[im][nt0], ah[im], bl4[0], bl4[1]);
                    mma_bf16(acc[im][nt0], al[im], bh4[0], bh4[1]);
                    mma_bf16(acc[im][nt1], ah[im], bh4[2], bh4[3]);
                    mma_bf16(acc[im][nt1], ah[im], bl4[2], bl4[3]);
                    mma_bf16(acc[im][nt1], al[im], bh4[2], bh4[3]);
                }
            }
        }
        __syncthreads();
        if (kt + 2 < nkt) GPF(kt + 2, kt & 1);
    }
#undef GPF

    const int g = lid >> 2, q = lid & 3;
    if (MODE == 0) {
#pragma unroll
        for (int im = 0; im < 2; ++im) {
            const int row0 = m0 + wm * 32 + im * 16 + g;
#pragma unroll
            for (int nt = 0; nt < 8; ++nt) {
                const int col = n0 + wn * 64 + nt * 8 + q * 2;
                float b0 = 0.f, b1 = 0.f;
                if (bias) { b0 = bias[col]; b1 = bias[col + 1]; }
                float2 v0 = make_float2(acc[im][nt][0] + b0, acc[im][nt][1] + b1);
                float2 v1 = make_float2(acc[im][nt][2] + b0, acc[im][nt][3] + b1);
                *(float2*)(C + (size_t)row0 * Nc + col)       = v0;
                *(float2*)(C + (size_t)(row0 + 8) * Nc + col) = v1;
            }
        }
    } else {
#pragma unroll
        for (int im = 0; im < 2; ++im) {
            const int row0 = m0 + wm * 32 + im * 16 + g;
#pragma unroll
            for (int nt = 0; nt < 8; ++nt) {
                const int col = n0 + wn * 64 + nt * 8 + q * 2;
                const int sect = col / 768, rem = col - sect * 768;
                const int h = rem >> 6, d = rem & 63;
                __nv_bfloat16 *dh, *dl;
                float sc;
                if (sect == 0)      { dh = qh_; dl = ql_; sc = 0.125f; }
                else if (sect == 1) { dh = kh_; dl = kl_; sc = 1.0f; }
                else                { dh = vh_; dl = vl_; sc = 1.0f; }
#pragma unroll
                for (int rr = 0; rr < 2; ++rr) {
                    const int row = row0 + rr * 8;
                    float v0 = acc[im][nt][rr * 2 + 0] * sc;
                    float v1 = acc[im][nt][rr * 2 + 1] * sc;
                    uint32_t hh, ll;
                    split_pack(v0, v1, hh, ll);
                    size_t off = ((size_t)(row >> 10) * 12 + h) * 65536
                               + (size_t)(row & 1023) * 64 + d;
                    *(uint32_t*)(dh + off) = hh;
                    *(uint32_t*)(dl + off) = ll;
                }
            }
        }
    }
}

// ---------------- HMMA bf16x3 flash attention --------------------------------
// CTA = (qtile of 128 rows, bh). 8 warps; warp w owns q-rows w*16..+15.
// Bk = 64, 2-stage cp.async pipeline on K/V (hi+lo).
#define AST     144                 // 64 bf16 = 128B + 16B pad
#define A_KOFF  0
#define A_KLOFF 9216
#define A_VOFF  18432
#define A_VLOFF 27648
#define ASTAGE  36864
#define ATTN_SMEM (2 * ASTAGE)      // 73728; Q staged through stage area

__global__ void __launch_bounds__(256, 2) attn_hmma(
    const __nv_bfloat16* __restrict__ qh, const __nv_bfloat16* __restrict__ ql,
    const __nv_bfloat16* __restrict__ kh, const __nv_bfloat16* __restrict__ kl,
    const __nv_bfloat16* __restrict__ vh, const __nv_bfloat16* __restrict__ vl,
    __nv_bfloat16* __restrict__ ah, __nv_bfloat16* __restrict__ al)
{
    extern __shared__ char sm_[];
    const uint32_t sb = smem_u32(sm_);
    const int tid = threadIdx.x, wid = tid >> 5, lid = tid & 31;
    const int g = lid >> 2, q = lid & 3;
    const int bh = blockIdx.y, qt = blockIdx.x;

    const size_t hb = (size_t)bh << 16;  // bh * 1024 * 64
    const __nv_bfloat16* Qh = qh + hb + (size_t)qt * 128 * 64;
    const __nv_bfloat16* Ql = ql + hb + (size_t)qt * 128 * 64;
    const __nv_bfloat16* Kh = kh + hb;
    const __nv_bfloat16* Kl = kl + hb;
    const __nv_bfloat16* Vh = vh + hb;
    const __nv_bfloat16* Vl = vl + hb;

    // ---- stage Q through smem, extract fragments to registers ----
#pragma unroll
    for (int it = 0; it < 4; ++it) {
        int idx = tid + it * 256;            // 0..1023
        int row = idx >> 3, c = idx & 7;
        *(uint4*)(sm_ + row * AST + c * 16) =
            *(const uint4*)(Qh + (size_t)row * 64 + c * 8);
        *(uint4*)(sm_ + 18432 + row * AST + c * 16) =
            *(const uint4*)(Ql + (size_t)row * 64 + c * 8);
    }
    __syncthreads();

    uint32_t qfh[4][4], qfl[4][4];
    {
        const uint32_t aoff = (wid * 16 + (lid & 15)) * AST + ((lid >> 4) << 4);
#pragma unroll
        for (int kc = 0; kc < 4; ++kc) {
            ldsm_x4(qfh[kc], sb + aoff + kc * 32);
            ldsm_x4(qfl[kc], sb + 18432 + aoff + kc * 32);
        }
    }
    __syncthreads();

    float mrow[2] = {-1e30f, -1e30f}, lrow[2] = {0.f, 0.f};
    float o[8][4];
#pragma unroll
    for (int i = 0; i < 8; ++i)
#pragma unroll
        for (int j = 0; j < 4; ++j) o[i][j] = 0.f;

    const int prow = tid >> 3, pc = tid & 7;  // 32 rows/iter x 8 16B-cols
#define APF(kt, stage) do {                                                       \
    uint32_t s0 = sb + (stage) * ASTAGE;                                          \
    _Pragma("unroll")                                                             \
    for (int half = 0; half < 2; ++half) {                                        \
        int row = prow + half * 32;                                               \
        uint32_t d = s0 + row * AST + pc * 16;                                    \
        size_t go = (size_t)((kt) * 64 + row) * 64 + pc * 8;                      \
        CP_ASYNC16(d + A_KOFF,  Kh + go);                                         \
        CP_ASYNC16(d + A_KLOFF, Kl + go);                                         \
        CP_ASYNC16(d + A_VOFF,  Vh + go);                                         \
        CP_ASYNC16(d + A_VLOFF, Vl + go);                                         \
    }                                                                             \
    CP_COMMIT();                                                                  \
} while (0)

    APF(0, 0);
    APF(1, 1);

    const uint32_t boff = ((lid & 7) + ((lid >> 4) << 3)) * AST + (((lid >> 3) & 1) << 4);
    const uint32_t voff = (lid & 15) * AST + ((lid >> 4) << 4);

    for (int kt = 0; kt < 16; ++kt) {
        if (kt == 15) { CP_WAIT(0); } else { CP_WAIT(1); }
        __syncthreads();
        const uint32_t st = sb + (kt & 1) * ASTAGE;

        // ---- S = Q K^T (bf16x3) ----
        float s[8][4];
#pragma unroll
        for (int i = 0; i < 8; ++i)
#pragma unroll
            for (int j = 0; j < 4; ++j) s[i][j] = 0.f;

#pragma unroll
        for (int kc = 0; kc < 4; ++kc) {
#pragma unroll
            for (int p = 0; p < 4; ++p) {
                uint32_t bh4[4], bl4[4];
                const uint32_t ba = st + p * 16 * AST + boff + kc * 32;
                ldsm_x4(bh4, ba + A_KOFF);
                ldsm_x4(bl4, ba + A_KLOFF);
                mma_bf16(s[2 * p],     qfh[kc], bh4[0], bh4[1]);
                mma_bf16(s[2 * p],     qfh[kc], bl4[0], bl4[1]);
                mma_bf16(s[2 * p],     qfl[kc], bh4[0], bh4[1]);
                mma_bf16(s[2 * p + 1], qfh[kc], bh4[2], bh4[3]);
                mma_bf16(s[2 * p + 1], qfh[kc], bl4[2], bl4[3]);
                mma_bf16(s[2 * p + 1], qfl[kc], bh4[2], bh4[3]);
            }
        }

        // ---- online softmax (rows g, g+8; reduce over 4 lanes of quad) ----
#pragma unroll
        for (int r = 0; r < 2; ++r) {
            float mx = -1e30f;
#pragma unroll
            for (int nt = 0; nt < 8; ++nt)
                mx = fmaxf(mx, fmaxf(s[nt][2 * r], s[nt][2 * r + 1]));
            mx = fmaxf(mx, __shfl_xor_sync(0xffffffffu, mx, 1));
            mx = fmaxf(mx, __shfl_xor_sync(0xffffffffu, mx, 2));
            float mn = fmaxf(mrow[r], mx);
            float alpha = __expf(mrow[r] - mn);
            mrow[r] = mn;
            float sum = 0.f;
#pragma unroll
            for (int nt = 0; nt < 8; ++nt) {
                float p0 = __expf(s[nt][2 * r]     - mn);
                float p1 = __expf(s[nt][2 * r + 1] - mn);
                s[nt][2 * r] = p0; s[nt][2 * r + 1] = p1;
                sum += p0 + p1;
            }
            sum += __shfl_xor_sync(0xffffffffu, sum, 1);
            sum += __shfl_xor_sync(0xffffffffu, sum, 2);
            lrow[r] = lrow[r] * alpha + sum;
#pragma unroll
            for (int nt = 0; nt < 8; ++nt) {
                o[nt][2 * r]     *= alpha;
                o[nt][2 * r + 1] *= alpha;
            }
        }

        // ---- O += P V (bf16x3), P from S fragments in-register ----
#pragma unroll
        for (int t = 0; t < 4; ++t) {
            uint32_t pah[4], pal[4];
            split_pack(s[2 * t][0],     s[2 * t][1],     pah[0], pal[0]);
            split_pack(s[2 * t][2],     s[2 * t][3],     pah[1], pal[1]);
            split_pack(s[2 * t + 1][0], s[2 * t + 1][1], pah[2], pal[2]);
            split_pack(s[2 * t + 1][2], s[2 * t + 1][3], pah[3], pal[3]);
#pragma unroll
            for (int p = 0; p < 4; ++p) {
                uint32_t vh4[4], vl4[4];
                const uint32_t va = st + t * 16 * AST + voff + p * 32;
                ldsm_x4_t(vh4, va + A_VOFF);
                ldsm_x4_t(vl4, va + A_VLOFF);
                mma_bf16(o[2 * p],     pah, vh4[0], vh4[1]);
                mma_bf16(o[2 * p],     pah, vl4[0], vl4[1]);
                mma_bf16(o[2 * p],     pal, vh4[0], vh4[1]);
                mma_bf16(o[2 * p + 1], pah, vh4[2], vh4[3]);
                mma_bf16(o[2 * p + 1], pah, vl4[2], vl4[3]);
                mma_bf16(o[2 * p + 1], pal, vh4[2], vh4[3]);
            }
        }

        __syncthreads();
        if (kt + 2 < 16) APF(kt + 2, kt & 1);
    }
#undef APF

    // ---- epilogue: normalize + split-write into [8192,768] proj input ----
    const int b = bh / NH_, h = bh - b * NH_;
    const float inv0 = 1.f / lrow[0], inv1 = 1.f / lrow[1];
    const int row0 = b * 1024 + qt * 128 + wid * 16 + g;
#pragma unroll
    for (int nt = 0; nt < 8; ++nt) {
        const int col = h * 64 + nt * 8 + q * 2;
        uint32_t hh, ll;
        split_pack(o[nt][0] * inv0, o[nt][1] * inv0, hh, ll);
        size_t off0 = (size_t)row0 * DIM_ + col;
        *(uint32_t*)(ah + off0) = hh;
        *(uint32_t*)(al + off0) = ll;
        split_pack(o[nt][2] * inv1, o[nt][3] * inv1, hh, ll);
        size_t off1 = (size_t)(row0 + 8) * DIM_ + col;
        *(uint32_t*)(ah + off1) = hh;
        *(uint32_t*)(al + off1) = ll;
    }
}

// ---------------------------------------------------------------------------
extern "C" void kernel_launch(void* const* d_in, const int* in_sizes, int n_in,
                              void* d_out, int out_size)
{
    const float* x      = (const float*)d_in[0];
    const float* w_qkv  = (const float*)d_in[1];
    const float* w_proj = (const float*)d_in[2];
    const float* b_proj = (const float*)d_in[3];
    float* out = (float*)d_out;

    __nv_bfloat16 *xh, *xl, *ahp, *alp, *wqh, *wql, *wph, *wpl;
    __nv_bfloat16 *qh, *ql, *kh, *kl, *vh, *vl;
    cudaGetSymbolAddress((void**)&xh, g_x_hi);
    cudaGetSymbolAddress((void**)&xl, g_x_lo);
    cudaGetSymbolAddress((void**)&ahp, g_a_hi);
    cudaGetSymbolAddress((void**)&alp, g_a_lo);
    cudaGetSymbolAddress((void**)&wqh, g_wqT_hi);
    cudaGetSymbolAddress((void**)&wql, g_wqT_lo);
    cudaGetSymbolAddress((void**)&wph, g_wpT_hi);
    cudaGetSymbolAddress((void**)&wpl, g_wpT_lo);
    cudaGetSymbolAddress((void**)&qh, g_q_hi);
    cudaGetSymbolAddress((void**)&ql, g_q_lo);
    cudaGetSymbolAddress((void**)&kh, g_k_hi);
    cudaGetSymbolAddress((void**)&kl, g_k_lo);
    cudaGetSymbolAddress((void**)&vh, g_v_hi);
    cudaGetSymbolAddress((void**)&vl, g_v_lo);

    cudaFuncSetAttribute(gemm_bf16x3<0>,
        cudaFuncAttributeMaxDynamicSharedMemorySize, GEMM_SMEM);
    cudaFuncSetAttribute(gemm_bf16x3<1>,
        cudaFuncAttributeMaxDynamicSharedMemorySize, GEMM_SMEM);
    cudaFuncSetAttribute(attn_hmma,
        cudaFuncAttributeMaxDynamicSharedMemorySize, ATTN_SMEM);

    const int M = MROWS;  // 8192

    // 0) input split + weight transposed splits
    {
        int n4 = M * DIM_ / 4;
        split_f32<<<(n4 + 255) / 256, 256>>>(x, xh, xl, n4);
        transpose_split<<<dim3(QKVC_ / 32, DIM_ / 32), 256>>>(w_qkv, wqh, wql, DIM_, QKVC_);
        transpose_split<<<dim3(DIM_ / 32, DIM_ / 32), 256>>>(w_proj, wph, wpl, DIM_, DIM_);
    }

    // 1) QKV projection -> split per-head q/k/v (q pre-scaled by 0.125)
    gemm_bf16x3<1><<<dim3(QKVC_ / 128, M / 128), 256, GEMM_SMEM>>>(
        xh, xl, wqh, wql, nullptr, nullptr, QKVC_, DIM_,
        qh, ql, kh, kl, vh, vl);

    // 2) HMMA flash attention -> split proj input
    attn_hmma<<<dim3(N_ / 128, B_ * NH_), 256, ATTN_SMEM>>>(
        qh, ql, kh, kl, vh, vl, ahp, alp);

    // 3) output projection + bias -> out
    gemm_bf16x3<0><<<dim3(DIM_ / 128, M / 128), 256, GEMM_SMEM>>>(
        ahp, alp, wph, wpl, b_proj, out, DIM_, DIM_,
        nullptr, nullptr, nullptr, nullptr, nullptr, nullptr);
}

// round 5
// speedup vs baseline: 3.0617x; 1.1660x over previous
#include <cuda_runtime.h>
#include <cuda_bf16.h>
#include <cstdint>
#include <math.h>

#define B_    8
#define N_    1024
#define DIM_  768
#define NH_   12
#define HD_   64
#define QKVC_ 2304
#define MROWS (B_*N_)   // 8192

// ---------------- scratch (__device__ globals) ------------------------------
static __device__ __nv_bfloat16 g_x_hi[(size_t)MROWS * DIM_];
static __device__ __nv_bfloat16 g_x_lo[(size_t)MROWS * DIM_];
static __device__ __nv_bfloat16 g_a_hi[(size_t)MROWS * DIM_];
static __device__ __nv_bfloat16 g_a_lo[(size_t)MROWS * DIM_];
static __device__ __nv_bfloat16 g_wqT_hi[(size_t)QKVC_ * DIM_];
static __device__ __nv_bfloat16 g_wqT_lo[(size_t)QKVC_ * DIM_];
static __device__ __nv_bfloat16 g_wpT_hi[(size_t)DIM_ * DIM_];
static __device__ __nv_bfloat16 g_wpT_lo[(size_t)DIM_ * DIM_];
// per-head split qkv: [bh][n][d], bh = b*12+h
static __device__ __nv_bfloat16 g_q_hi[(size_t)MROWS * DIM_];
static __device__ __nv_bfloat16 g_q_lo[(size_t)MROWS * DIM_];
static __device__ __nv_bfloat16 g_k_hi[(size_t)MROWS * DIM_];
static __device__ __nv_bfloat16 g_k_lo[(size_t)MROWS * DIM_];
static __device__ __nv_bfloat16 g_v_hi[(size_t)MROWS * DIM_];
static __device__ __nv_bfloat16 g_v_lo[(size_t)MROWS * DIM_];

// ---------------- helpers ----------------------------------------------------
__device__ __forceinline__ uint32_t smem_u32(const void* p) {
    uint32_t a;
    asm("{ .reg .u64 t; cvta.to.shared.u64 t, %1; cvt.u32.u64 %0, t; }" : "=r"(a) : "l"(p));
    return a;
}
__device__ __forceinline__ void ldsm_x4(uint32_t* r, uint32_t addr) {
    asm volatile("ldmatrix.sync.aligned.m8n8.x4.shared.b16 {%0,%1,%2,%3}, [%4];"
                 : "=r"(r[0]), "=r"(r[1]), "=r"(r[2]), "=r"(r[3]) : "r"(addr));
}
__device__ __forceinline__ void ldsm_x4_t(uint32_t* r, uint32_t addr) {
    asm volatile("ldmatrix.sync.aligned.m8n8.x4.trans.shared.b16 {%0,%1,%2,%3}, [%4];"
                 : "=r"(r[0]), "=r"(r[1]), "=r"(r[2]), "=r"(r[3]) : "r"(addr));
}
__device__ __forceinline__ void mma_bf16(float* c, const uint32_t* a,
                                         uint32_t b0, uint32_t b1) {
    asm volatile("mma.sync.aligned.m16n8k16.row.col.f32.bf16.bf16.f32 "
        "{%0,%1,%2,%3}, {%4,%5,%6,%7}, {%8,%9}, {%0,%1,%2,%3};"
        : "+f"(c[0]), "+f"(c[1]), "+f"(c[2]), "+f"(c[3])
        : "r"(a[0]), "r"(a[1]), "r"(a[2]), "r"(a[3]), "r"(b0), "r"(b1));
}
__device__ __forceinline__ uint32_t pack_bf16x2(float lo, float hi) {
    uint32_t d;
    asm("cvt.rn.bf16x2.f32 %0, %1, %2;" : "=r"(d) : "f"(hi), "f"(lo));
    return d;
}
__device__ __forceinline__ void split_pack(float v0, float v1,
                                           uint32_t& h, uint32_t& l) {
    h = pack_bf16x2(v0, v1);
    float f0 = __uint_as_float(h << 16);
    float f1 = __uint_as_float(h & 0xffff0000u);
    l = pack_bf16x2(v0 - f0, v1 - f1);
}
#define CP_ASYNC16(dst, src) \
    asm volatile("cp.async.cg.shared.global [%0], [%1], 16;" :: "r"(dst), "l"(src) : "memory")
#define CP_COMMIT() asm volatile("cp.async.commit_group;" ::: "memory")
#define CP_WAIT(n)  asm volatile("cp.async.wait_group %0;" :: "n"(n) : "memory")

// ---------------- conversion kernels ----------------------------------------
__global__ void __launch_bounds__(256) split_f32(
    const float* __restrict__ in, __nv_bfloat16* __restrict__ hi,
    __nv_bfloat16* __restrict__ lo, int n4)
{
    int i = blockIdx.x * blockDim.x + threadIdx.x;
    if (i >= n4) return;
    float4 v = ((const float4*)in)[i];
    uint32_t h0, l0, h1, l1;
    split_pack(v.x, v.y, h0, l0);
    split_pack(v.z, v.w, h1, l1);
    ((uint32_t*)hi)[2 * i]     = h0;
    ((uint32_t*)hi)[2 * i + 1] = h1;
    ((uint32_t*)lo)[2 * i]     = l0;
    ((uint32_t*)lo)[2 * i + 1] = l1;
}

__global__ void __launch_bounds__(256) transpose_split(
    const float* __restrict__ W, __nv_bfloat16* __restrict__ hiT,
    __nv_bfloat16* __restrict__ loT, int K, int Nc)
{
    __shared__ float t[32][33];
    const int n0 = blockIdx.x * 32, k0 = blockIdx.y * 32;
    const int tx = threadIdx.x & 31, ty = threadIdx.x >> 5;
#pragma unroll
    for (int i = 0; i < 32; i += 8)
        t[ty + i][tx] = W[(size_t)(k0 + ty + i) * Nc + n0 + tx];
    __syncthreads();
#pragma unroll
    for (int i = 0; i < 32; i += 8) {
        float v = t[tx][ty + i];
        __nv_bfloat16 h = __float2bfloat16(v);
        __nv_bfloat16 l = __float2bfloat16(v - __bfloat162float(h));
        size_t o = (size_t)(n0 + ty + i) * K + k0 + tx;
        hiT[o] = h;
        loT[o] = l;
    }
}

// ---------------- HMMA bf16x3 GEMM (3-stage cp.async, 1 sync/iter) ----------
// Tiles: 128 rows x 32 bf16 = 64B rows, XOR swizzle c ^= (row>>1)&3.
#define GT       8192                // tile bytes
#define GSTAGE   (4 * GT)            // Ahi, Alo, Bhi, Blo = 32768
#define GEMM_SMEM (3 * GSTAGE)       // 98304

template<int MODE>
__global__ void __launch_bounds__(256, 2) gemm_bf16x3(
    const __nv_bfloat16* __restrict__ Ahi, const __nv_bfloat16* __restrict__ Alo,
    const __nv_bfloat16* __restrict__ BhiT, const __nv_bfloat16* __restrict__ BloT,
    const float* __restrict__ bias, float* __restrict__ C, int Nc, int K,
    __nv_bfloat16* qh_, __nv_bfloat16* ql_, __nv_bfloat16* kh_,
    __nv_bfloat16* kl_, __nv_bfloat16* vh_, __nv_bfloat16* vl_)
{
    extern __shared__ char gsm[];
    const uint32_t sb = smem_u32(gsm);
    const int tid = threadIdx.x, wid = tid >> 5, lid = tid & 31;
    const int wm = wid >> 1, wn = wid & 1;
    const int m0 = blockIdx.y << 7, n0 = blockIdx.x << 7;

    const __nv_bfloat16* pAh = Ahi  + (size_t)m0 * K;
    const __nv_bfloat16* pAl = Alo  + (size_t)m0 * K;
    const __nv_bfloat16* pBh = BhiT + (size_t)n0 * K;
    const __nv_bfloat16* pBl = BloT + (size_t)n0 * K;

    float acc[2][8][4];
#pragma unroll
    for (int i = 0; i < 2; ++i)
#pragma unroll
        for (int j = 0; j < 8; ++j)
#pragma unroll
            for (int k = 0; k < 4; ++k) acc[i][j][k] = 0.f;

    const int nkt = K >> 5;

    const int prow = tid >> 2, pc4 = tid & 3;
#define GPF(kt, stage) do {                                                      \
    uint32_t s0 = sb + (stage) * GSTAGE;                                         \
    _Pragma("unroll")                                                            \
    for (int half = 0; half < 2; ++half) {                                       \
        int row = prow + half * 64;                                              \
        uint32_t d = s0 + row * 64 + ((pc4 ^ ((row >> 1) & 3)) << 4);            \
        size_t go = (size_t)row * K + (size_t)(kt) * 32 + pc4 * 8;               \
        CP_ASYNC16(d + 0 * GT, pAh + go);                                        \
        CP_ASYNC16(d + 1 * GT, pAl + go);                                        \
        CP_ASYNC16(d + 2 * GT, pBh + go);                                        \
        CP_ASYNC16(d + 3 * GT, pBl + go);                                        \
    }                                                                            \
    CP_COMMIT();                                                                 \
} while (0)

    GPF(0, 0);
    GPF(1, 1);

    // per-lane ldmatrix row bases + swizzle keys
    uint32_t abase[2], asw[2], bbase[4], bsw[4];
    const int acb = lid >> 4;          // A col bit
    const int bcb = (lid >> 3) & 1;    // B col bit
#pragma unroll
    for (int im = 0; im < 2; ++im) {
        int ar = wm * 32 + (lid & 15) + im * 16;
        abase[im] = ar * 64;
        asw[im] = (ar >> 1) & 3;
    }
#pragma unroll
    for (int p = 0; p < 4; ++p) {
        int br = wn * 64 + (lid & 7) + ((lid >> 4) << 3) + p * 16;
        bbase[p] = br * 64;
        bsw[p] = (br >> 1) & 3;
    }

    int scur = 0;
    for (int kt = 0; kt < nkt; ++kt) {
        if (kt == nkt - 1) { CP_WAIT(0); } else { CP_WAIT(1); }
        __syncthreads();
        const uint32_t st = sb + scur * GSTAGE;

#pragma unroll
        for (int kc = 0; kc < 2; ++kc) {
            uint32_t ah[2][4], al[2][4];
#pragma unroll
            for (int im = 0; im < 2; ++im) {
                uint32_t ao = st + abase[im]
                            + (((uint32_t)(kc * 2 + acb) ^ asw[im]) << 4);
                ldsm_x4(ah[im], ao);
                ldsm_x4(al[im], ao + GT);
            }
#pragma unroll
            for (int p = 0; p < 4; ++p) {
                uint32_t bh4[4], bl4[4];
                uint32_t bo = st + 2 * GT + bbase[p]
                            + (((uint32_t)(kc * 2 + bcb) ^ bsw[p]) << 4);
                ldsm_x4(bh4, bo);
                ldsm_x4(bl4, bo + GT);
                const int nt0 = p * 2, nt1 = p * 2 + 1;
#pragma unroll
                for (int im = 0; im < 2; ++im) {
                    mma_bf16(acc[im][nt0], ah[im], bh4[0], bh4[1]);
                    mma_bf16(acc[im][nt1], ah[im], bh4[2], bh4[3]);
                    mma_bf16(acc[im][nt0], ah[im], bl4[0], bl4[1]);
                    mma_bf16(acc[im][nt1], ah[im], bl4[2], bl4[3]);
                    mma_bf16(acc[im][nt0], al[im], bh4[0], bh4[1]);
                    mma_bf16(acc[im][nt1], al[im], bh4[2], bh4[3]);
                }
            }
        }
        if (kt + 2 < nkt) {
            int spf = scur + 2; if (spf >= 3) spf -= 3;
            GPF(kt + 2, spf);
        }
        if (++scur == 3) scur = 0;
    }
#undef GPF

    const int g = lid >> 2, q = lid & 3;
    if (MODE == 0) {
#pragma unroll
        for (int im = 0; im < 2; ++im) {
            const int row0 = m0 + wm * 32 + im * 16 + g;
#pragma unroll
            for (int nt = 0; nt < 8; ++nt) {
                const int col = n0 + wn * 64 + nt * 8 + q * 2;
                float b0 = 0.f, b1 = 0.f;
                if (bias) { b0 = bias[col]; b1 = bias[col + 1]; }
                float2 v0 = make_float2(acc[im][nt][0] + b0, acc[im][nt][1] + b1);
                float2 v1 = make_float2(acc[im][nt][2] + b0, acc[im][nt][3] + b1);
                *(float2*)(C + (size_t)row0 * Nc + col)       = v0;
                *(float2*)(C + (size_t)(row0 + 8) * Nc + col) = v1;
            }
        }
    } else {
#pragma unroll
        for (int im = 0; im < 2; ++im) {
            const int row0 = m0 + wm * 32 + im * 16 + g;
#pragma unroll
            for (int nt = 0; nt < 8; ++nt) {
                const int col = n0 + wn * 64 + nt * 8 + q * 2;
                const int sect = col / 768, rem = col - sect * 768;
                const int h = rem >> 6, d = rem & 63;
                __nv_bfloat16 *dh, *dl;
                float sc;
                if (sect == 0)      { dh = qh_; dl = ql_; sc = 0.125f; }
                else if (sect == 1) { dh = kh_; dl = kl_; sc = 1.0f; }
                else                { dh = vh_; dl = vl_; sc = 1.0f; }
#pragma unroll
                for (int rr = 0; rr < 2; ++rr) {
                    const int row = row0 + rr * 8;
                    float v0 = acc[im][nt][rr * 2 + 0] * sc;
                    float v1 = acc[im][nt][rr * 2 + 1] * sc;
                    uint32_t hh, ll;
                    split_pack(v0, v1, hh, ll);
                    size_t off = ((size_t)(row >> 10) * 12 + h) * 65536
                               + (size_t)(row & 1023) * 64 + d;
                    *(uint32_t*)(dh + off) = hh;
                    *(uint32_t*)(dl + off) = ll;
                }
            }
        }
    }
}

// ---------------- HMMA bf16x3 flash attention (3-stage, 1 sync/iter) --------
// K/V tiles: 64 rows x 64 bf16 = 128B rows, XOR swizzle c ^= row&7.
#define AT      8192                 // one K or V tile
#define ASTAGE  (4 * AT)             // Kh, Kl, Vh, Vl = 32768
#define ATTN_SMEM (3 * ASTAGE)       // 98304; Q staged through stage 0

__global__ void __launch_bounds__(256, 2) attn_hmma(
    const __nv_bfloat16* __restrict__ qh, const __nv_bfloat16* __restrict__ ql,
    const __nv_bfloat16* __restrict__ kh, const __nv_bfloat16* __restrict__ kl,
    const __nv_bfloat16* __restrict__ vh, const __nv_bfloat16* __restrict__ vl,
    __nv_bfloat16* __restrict__ ah, __nv_bfloat16* __restrict__ al)
{
    extern __shared__ char sm_[];
    const uint32_t sb = smem_u32(sm_);
    const int tid = threadIdx.x, wid = tid >> 5, lid = tid & 31;
    const int g = lid >> 2, q = lid & 3;
    const int bh = blockIdx.y, qt = blockIdx.x;

    const size_t hb = (size_t)bh << 16;
    const __nv_bfloat16* Qh = qh + hb + (size_t)qt * 128 * 64;
    const __nv_bfloat16* Ql = ql + hb + (size_t)qt * 128 * 64;
    const __nv_bfloat16* Kh = kh + hb;
    const __nv_bfloat16* Kl = kl + hb;
    const __nv_bfloat16* Vh = vh + hb;
    const __nv_bfloat16* Vl = vl + hb;

    // ---- stage Q through stage-0 smem (swizzled 128B rows), extract frags ----
#pragma unroll
    for (int it = 0; it < 4; ++it) {
        int idx = tid + it * 256;            // 0..1023
        int row = idx >> 3, c = idx & 7;
        uint32_t d = row * 128 + ((c ^ (row & 7)) << 4);
        *(uint4*)(sm_ + d)         = *(const uint4*)(Qh + (size_t)row * 64 + c * 8);
        *(uint4*)(sm_ + 16384 + d) = *(const uint4*)(Ql + (size_t)row * 64 + c * 8);
    }
    __syncthreads();

    uint32_t qfh[4][4], qfl[4][4];
    {
        const int arq = wid * 16 + (lid & 15);
        const uint32_t qbase = arq * 128;
        const uint32_t qsw = arq & 7;
        const int acb = lid >> 4;
#pragma unroll
        for (int kc = 0; kc < 4; ++kc) {
            uint32_t ao = sb + qbase + (((uint32_t)(kc * 2 + acb) ^ qsw) << 4);
            ldsm_x4(qfh[kc], ao);
            ldsm_x4(qfl[kc], ao + 16384);
        }
    }
    __syncthreads();

    float mrow[2] = {-1e30f, -1e30f}, lrow[2] = {0.f, 0.f};
    float o[8][4];
#pragma unroll
    for (int i = 0; i < 8; ++i)
#pragma unroll
        for (int j = 0; j < 4; ++j) o[i][j] = 0.f;

    const int prow = tid >> 3, pc = tid & 7;
#define APF(kt, stage) do {                                                       \
    uint32_t s0 = sb + (stage) * ASTAGE;                                          \
    _Pragma("unroll")                                                             \
    for (int half = 0; half < 2; ++half) {                                        \
        int row = prow + half * 32;                                               \
        uint32_t d = s0 + row * 128 + ((pc ^ (row & 7)) << 4);                    \
        size_t go = (size_t)((kt) * 64 + row) * 64 + pc * 8;                      \
        CP_ASYNC16(d + 0 * AT, Kh + go);                                          \
        CP_ASYNC16(d + 1 * AT, Kl + go);                                          \
        CP_ASYNC16(d + 2 * AT, Vh + go);                                          \
        CP_ASYNC16(d + 3 * AT, Vl + go);                                          \
    }                                                                             \
    CP_COMMIT();                                                                  \
} while (0)

    APF(0, 0);
    APF(1, 1);

    // per-lane row bases for K (S's B operand) and V (trans)
    uint32_t kbase[4], ksw[4], vbase[4], vsw[4];
    const int bcb = (lid >> 3) & 1;
    const int vcb = lid >> 4;
#pragma unroll
    for (int p = 0; p < 4; ++p) {
        int br = (lid & 7) + ((lid >> 4) << 3) + p * 16;
        kbase[p] = br * 128; ksw[p] = br & 7;
        int vr = (lid & 15) + p * 16;          // indexed by t at use site
        vbase[p] = vr * 128; vsw[p] = vr & 7;
    }

    int scur = 0;
    for (int kt = 0; kt < 16; ++kt) {
        if (kt == 15) { CP_WAIT(0); } else { CP_WAIT(1); }
        __syncthreads();
        const uint32_t st = sb + scur * ASTAGE;

        // ---- S = Q K^T (bf16x3) ----
        float s[8][4];
#pragma unroll
        for (int i = 0; i < 8; ++i)
#pragma unroll
            for (int j = 0; j < 4; ++j) s[i][j] = 0.f;

#pragma unroll
        for (int kc = 0; kc < 4; ++kc) {
#pragma unroll
            for (int p = 0; p < 4; ++p) {
                uint32_t bh4[4], bl4[4];
                uint32_t bo = st + kbase[p]
                            + (((uint32_t)(kc * 2 + bcb) ^ ksw[p]) << 4);
                ldsm_x4(bh4, bo);
                ldsm_x4(bl4, bo + AT);
                mma_bf16(s[2 * p],     qfh[kc], bh4[0], bh4[1]);
                mma_bf16(s[2 * p + 1], qfh[kc], bh4[2], bh4[3]);
                mma_bf16(s[2 * p],     qfh[kc], bl4[0], bl4[1]);
                mma_bf16(s[2 * p + 1], qfh[kc], bl4[2], bl4[3]);
                mma_bf16(s[2 * p],     qfl[kc], bh4[0], bh4[1]);
                mma_bf16(s[2 * p + 1], qfl[kc], bh4[2], bh4[3]);
            }
        }

        // ---- online softmax ----
#pragma unroll
        for (int r = 0; r < 2; ++r) {
            float mx = -1e30f;
#pragma unroll
            for (int nt = 0; nt < 8; ++nt)
                mx = fmaxf(mx, fmaxf(s[nt][2 * r], s[nt][2 * r + 1]));
            mx = fmaxf(mx, __shfl_xor_sync(0xffffffffu, mx, 1));
            mx = fmaxf(mx, __shfl_xor_sync(0xffffffffu, mx, 2));
            float mn = fmaxf(mrow[r], mx);
            float alpha = __expf(mrow[r] - mn);
            mrow[r] = mn;
            float sum = 0.f;
#pragma unroll
            for (int nt = 0; nt < 8; ++nt) {
                float p0 = __expf(s[nt][2 * r]     - mn);
                float p1 = __expf(s[nt][2 * r + 1] - mn);
                s[nt][2 * r] = p0; s[nt][2 * r + 1] = p1;
                sum += p0 + p1;
            }
            sum += __shfl_xor_sync(0xffffffffu, sum, 1);
            sum += __shfl_xor_sync(0xffffffffu, sum, 2);
            lrow[r] = lrow[r] * alpha + sum;
#pragma unroll
            for (int nt = 0; nt < 8; ++nt) {
                o[nt][2 * r]     *= alpha;
                o[nt][2 * r + 1] *= alpha;
            }
        }

        // ---- O += P V (bf16x3) ----
#pragma unroll
        for (int t = 0; t < 4; ++t) {
            uint32_t pah[4], pal[4];
            split_pack(s[2 * t][0],     s[2 * t][1],     pah[0], pal[0]);
            split_pack(s[2 * t][2],     s[2 * t][3],     pah[1], pal[1]);
            split_pack(s[2 * t + 1][0], s[2 * t + 1][1], pah[2], pal[2]);
            split_pack(s[2 * t + 1][2], s[2 * t + 1][3], pah[3], pal[3]);
#pragma unroll
            for (int p = 0; p < 4; ++p) {
                uint32_t vh4[4], vl4[4];
                uint32_t vo = st + 2 * AT + vbase[t]
                            + (((uint32_t)(p * 2 + vcb) ^ vsw[t]) << 4);
                ldsm_x4_t(vh4, vo);
                ldsm_x4_t(vl4, vo + AT);
                mma_bf16(o[2 * p],     pah, vh4[0], vh4[1]);
                mma_bf16(o[2 * p + 1], pah, vh4[2], vh4[3]);
                mma_bf16(o[2 * p],     pah, vl4[0], vl4[1]);
                mma_bf16(o[2 * p + 1], pah, vl4[2], vl4[3]);
                mma_bf16(o[2 * p],     pal, vh4[0], vh4[1]);
                mma_bf16(o[2 * p + 1], pal, vh4[2], vh4[3]);
            }
        }

        if (kt + 2 < 16) {
            int spf = scur + 2; if (spf >= 3) spf -= 3;
            APF(kt + 2, spf);
        }
        if (++scur == 3) scur = 0;
    }
#undef APF

    // ---- epilogue: normalize + split-write proj input ----
    const int b = bh / NH_, h = bh - b * NH_;
    const float inv0 = 1.f / lrow[0], inv1 = 1.f / lrow[1];
    const int row0 = b * 1024 + qt * 128 + wid * 16 + g;
#pragma unroll
    for (int nt = 0; nt < 8; ++nt) {
        const int col = h * 64 + nt * 8 + q * 2;
        uint32_t hh, ll;
        split_pack(o[nt][0] * inv0, o[nt][1] * inv0, hh, ll);
        size_t off0 = (size_t)row0 * DIM_ + col;
        *(uint32_t*)(ah + off0) = hh;
        *(uint32_t*)(al + off0) = ll;
        split_pack(o[nt][2] * inv1, o[nt][3] * inv1, hh, ll);
        size_t off1 = (size_t)(row0 + 8) * DIM_ + col;
        *(uint32_t*)(ah + off1) = hh;
        *(uint32_t*)(al + off1) = ll;
    }
}

// ---------------------------------------------------------------------------
extern "C" void kernel_launch(void* const* d_in, const int* in_sizes, int n_in,
                              void* d_out, int out_size)
{
    const float* x      = (const float*)d_in[0];
    const float* w_qkv  = (const float*)d_in[1];
    const float* w_proj = (const float*)d_in[2];
    const float* b_proj = (const float*)d_in[3];
    float* out = (float*)d_out;

    __nv_bfloat16 *xh, *xl, *ahp, *alp, *wqh, *wql, *wph, *wpl;
    __nv_bfloat16 *qh, *ql, *kh, *kl, *vh, *vl;
    cudaGetSymbolAddress((void**)&xh, g_x_hi);
    cudaGetSymbolAddress((void**)&xl, g_x_lo);
    cudaGetSymbolAddress((void**)&ahp, g_a_hi);
    cudaGetSymbolAddress((void**)&alp, g_a_lo);
    cudaGetSymbolAddress((void**)&wqh, g_wqT_hi);
    cudaGetSymbolAddress((void**)&wql, g_wqT_lo);
    cudaGetSymbolAddress((void**)&wph, g_wpT_hi);
    cudaGetSymbolAddress((void**)&wpl, g_wpT_lo);
    cudaGetSymbolAddress((void**)&qh, g_q_hi);
    cudaGetSymbolAddress((void**)&ql, g_q_lo);
    cudaGetSymbolAddress((void**)&kh, g_k_hi);
    cudaGetSymbolAddress((void**)&kl, g_k_lo);
    cudaGetSymbolAddress((void**)&vh, g_v_hi);
    cudaGetSymbolAddress((void**)&vl, g_v_lo);

    cudaFuncSetAttribute(gemm_bf16x3<0>,
        cudaFuncAttributeMaxDynamicSharedMemorySize, GEMM_SMEM);
    cudaFuncSetAttribute(gemm_bf16x3<1>,
        cudaFuncAttributeMaxDynamicSharedMemorySize, GEMM_SMEM);
    cudaFuncSetAttribute(attn_hmma,
        cudaFuncAttributeMaxDynamicSharedMemorySize, ATTN_SMEM);

    const int M = MROWS;

    {
        int n4 = M * DIM_ / 4;
        split_f32<<<(n4 + 255) / 256, 256>>>(x, xh, xl, n4);
        transpose_split<<<dim3(QKVC_ / 32, DIM_ / 32), 256>>>(w_qkv, wqh, wql, DIM_, QKVC_);
        transpose_split<<<dim3(DIM_ / 32, DIM_ / 32), 256>>>(w_proj, wph, wpl, DIM_, DIM_);
    }

    gemm_bf16x3<1><<<dim3(QKVC_ / 128, M / 128), 256, GEMM_SMEM>>>(
        xh, xl, wqh, wql, nullptr, nullptr, QKVC_, DIM_,
        qh, ql, kh, kl, vh, vl);

    attn_hmma<<<dim3(N_ / 128, B_ * NH_), 256, ATTN_SMEM>>>(
        qh, ql, kh, kl, vh, vl, ahp, alp);

    gemm_bf16x3<0><<<dim3(DIM_ / 128, M / 128), 256, GEMM_SMEM>>>(
        ahp, alp, wph, wpl, b_proj, out, DIM_, DIM_,
        nullptr, nullptr, nullptr, nullptr, nullptr, nullptr);
}